// round 9
// baseline (speedup 1.0000x reference)
#include <cuda_runtime.h>

typedef unsigned long long ull;

// Weights in global, built per replay by setup_kernel.
// g_WT[i]: interleaved transposed fusion weights:
//   d = k*64 + h*32 + g*4 + e  <->  c = g*8 + h*4 + e   (h<2, e<4, g<8)
//   so thread g's 8 cols live in two contiguous 16B chunks per k.
// g_WngT: plain transposed [k][c].
__device__ float g_WT[2][256 * 64];
__device__ float g_WngT[128 * 64];

__global__ void setup_kernel(const float* __restrict__ Wfp1,
                             const float* __restrict__ Wf1,
                             const float* __restrict__ Wng) {
    int tid = blockIdx.x * blockDim.x + threadIdx.x;
    int stride = gridDim.x * blockDim.x;
    for (int i = tid; i < 64 * 256; i += stride) {
        int c = i >> 8, k = i & 255;
        int g = c >> 3, h = (c >> 2) & 1, e = c & 3;
        int d = k * 64 + h * 32 + g * 4 + e;
        g_WT[0][d] = Wfp1[i];
        g_WT[1][d] = Wf1[i];
    }
    for (int i = tid; i < 64 * 128; i += stride) {
        int c = i >> 7, k = i & 127;
        g_WngT[k * 64 + c] = Wng[i];
    }
}

__device__ __forceinline__ float sigmoidf_(float x) {
    return __fdividef(1.0f, 1.0f + __expf(-x));
}
__device__ __forceinline__ float gatef_(float x, float rm) {
    return x * sigmoidf_(fabsf(x - rm));
}
__device__ __forceinline__ float leakyf_(float x) {
    return x > 0.0f ? x : 0.01f * x;
}
__device__ __forceinline__ void ffma2_(ull& d, ull a, ull b) {
    asm("fma.rn.f32x2 %0, %1, %2, %0;" : "+l"(d) : "l"(a), "l"(b));
}
__device__ __forceinline__ ull fmul2_(ull a, ull b) {
    ull r;
    asm("mul.rn.f32x2 %0, %1, %2;" : "=l"(r) : "l"(a), "l"(b));
    return r;
}
__device__ __forceinline__ ull dup2_(float x) {
    ull r;
    unsigned u = __float_as_uint(x);
    asm("mov.b64 %0, {%1, %1};" : "=l"(r) : "r"(u));
    return r;
}
__device__ __forceinline__ float2 unpk_(ull v) {
    float2 r;
    asm("mov.b64 {%0, %1}, %2;" : "=f"(r.x), "=f"(r.y) : "l"(v));
    return r;
}
__device__ __forceinline__ void st_dup2(float* p, float v) {
    *reinterpret_cast<float2*>(p) = make_float2(v, v);
}

__device__ __forceinline__ void copy16(float* __restrict__ dst,
                                       const float* __restrict__ src, int tid) {
    const float4* s = reinterpret_cast<const float4*>(src);
    float4* d = reinterpret_cast<float4*>(dst);
#pragma unroll
    for (int i = 0; i < 16; i++) d[tid + i * 256] = s[tid + i * 256];
}
__device__ __forceinline__ void copy8(float* __restrict__ dst,
                                      const float* __restrict__ src, int tid) {
    const float4* s = reinterpret_cast<const float4*>(src);
    float4* d = reinterpret_cast<float4*>(dst);
#pragma unroll
    for (int i = 0; i < 8; i++) d[tid + i * 256] = s[tid + i * 256];
}

// One 4-output matvec + sigmoid. Thread handles outputs q*4..q*4+3.
__device__ __forceinline__ void mv4(const float* __restrict__ in, int row,
                                    const float* __restrict__ W,
                                    const float* __restrict__ b, int q,
                                    float h[4]) {
    ull acc[4] = {0, 0, 0, 0};
#pragma unroll 4
    for (int k = 0; k < 64; k += 4) {
        ulonglong2 xv =
            __ldg(reinterpret_cast<const ulonglong2*>(in + row * 64 + k));
#pragma unroll
        for (int j = 0; j < 4; j++) {
            ulonglong2 w = __ldg(
                reinterpret_cast<const ulonglong2*>(W + (q * 4 + j) * 64 + k));
            ffma2_(acc[j], xv.x, w.x);
            ffma2_(acc[j], xv.y, w.y);
        }
    }
#pragma unroll
    for (int j = 0; j < 4; j++) {
        float2 p = unpk_(acc[j]);
        h[j] = sigmoidf_(p.x + p.y + __ldg(b + q * 4 + j));
    }
}

// 3 matvecs + pooling; writes dup'd factors into sMxd[8][128],
// sM2yd[4][128], sMzd[8][128] at column 2r. Thread (r = tid>>2, q = tid&3).
__device__ __forceinline__ void matvec_pool(
    const float* __restrict__ x, const float* __restrict__ y,
    const float* __restrict__ z, int row, float* __restrict__ sMxd,
    float* __restrict__ sM2yd, float* __restrict__ sMzd,
    const float* __restrict__ Wx, const float* __restrict__ bx,
    const float* __restrict__ Wy, const float* __restrict__ by,
    const float* __restrict__ Wz, const float* __restrict__ bz, int r, int q) {
    float h[4];
    mv4(x, row, Wx, bx, q, h);
    st_dup2(sMxd + (2 * q) * 128 + 2 * r, fmaxf(h[0], h[1]));
    st_dup2(sMxd + (2 * q + 1) * 128 + 2 * r, fmaxf(h[2], h[3]));
    mv4(y, row, Wy, by, q, h);
    st_dup2(sM2yd + q * 128 + 2 * r,
            fmaxf(fmaxf(h[0], h[1]), fmaxf(h[2], h[3])));
    mv4(z, row, Wz, bz, q, h);
    st_dup2(sMzd + (2 * q) * 128 + 2 * r, fmaxf(h[0], h[1]));
    st_dup2(sMzd + (2 * q + 1) * 128 + 2 * r, fmaxf(h[2], h[3]));
}

// Fusion GEMM, 2 rows (r0, r0+1) x 8 cols (g*8..g*8+7), col-pair packed accs.
// F[k = (ix*4+iy)*8 + t][row] = mx[ix]*m2y[iy]*mz[t].
// Weights interleaved; per t exactly 2 one-wavefront LDS.128.
// mz and m2y factors held in registers across the whole k loop.
__device__ __forceinline__ void gemm_fuse(
    const float* __restrict__ sW_, const float* __restrict__ sMxd,
    const float* __restrict__ sM2yd, const float* __restrict__ sMzd, int r0,
    int g, ull acc[2][4]) {
    ull mz2[2][8];
#pragma unroll
    for (int t = 0; t < 8; t++) {
        ulonglong2 m =
            *reinterpret_cast<const ulonglong2*>(sMzd + t * 128 + 2 * r0);
        mz2[0][t] = m.x;
        mz2[1][t] = m.y;
    }
    ull my2[2][4];
#pragma unroll
    for (int iy = 0; iy < 4; iy++) {
        ulonglong2 y =
            *reinterpret_cast<const ulonglong2*>(sM2yd + iy * 128 + 2 * r0);
        my2[0][iy] = y.x;
        my2[1][iy] = y.y;
    }
#pragma unroll 1
    for (int ix = 0; ix < 8; ix++) {
        ulonglong2 ma =
            *reinterpret_cast<const ulonglong2*>(sMxd + ix * 128 + 2 * r0);
#pragma unroll
        for (int iy = 0; iy < 4; iy++) {
            ull P0 = fmul2_(ma.x, my2[0][iy]);
            ull P1 = fmul2_(ma.y, my2[1][iy]);
            const float* wrow = sW_ + (ix * 4 + iy) * 512 + g * 4;
#pragma unroll
            for (int t = 0; t < 8; t++) {
                ulonglong2 w0 =
                    *reinterpret_cast<const ulonglong2*>(wrow + t * 64);
                ulonglong2 w1 =
                    *reinterpret_cast<const ulonglong2*>(wrow + t * 64 + 32);
                ull f0 = fmul2_(P0, mz2[0][t]);
                ull f1 = fmul2_(P1, mz2[1][t]);
                ffma2_(acc[0][0], f0, w0.x); ffma2_(acc[0][1], f0, w0.y);
                ffma2_(acc[0][2], f0, w1.x); ffma2_(acc[0][3], f0, w1.y);
                ffma2_(acc[1][0], f1, w0.x); ffma2_(acc[1][1], f1, w0.y);
                ffma2_(acc[1][2], f1, w1.x); ffma2_(acc[1][3], f1, w1.y);
            }
        }
    }
}

// Shared layout (floats):
//  sW    @ 0     : 16384
//  sGT   @ 16384 : 8704   ([128][68], col-major, rows padded)
//  sMxd  @ 25088 : 1024   ([8][128])
//  sM2yd @ 26112 : 512    ([4][128])
//  sMzd  @ 26624 : 1024   ([8][128])
//  total 27648 floats = 110592 B -> 2 CTAs/SM
#define OFF_GT 16384
#define OFF_MXD 25088
#define OFF_M2YD 26112
#define OFF_MZD 26624
#define SMEM_FLOATS 27648

__global__ void __launch_bounds__(256, 2) fusion_main(
    const float* __restrict__ a, const float* __restrict__ v,
    const float* __restrict__ l, const float* __restrict__ pa,
    const float* __restrict__ pv, const float* __restrict__ pl,
    const float* __restrict__ mean, const float* __restrict__ Wa,
    const float* __restrict__ ba, const float* __restrict__ Wv,
    const float* __restrict__ bv, const float* __restrict__ Wl,
    const float* __restrict__ bl, const float* __restrict__ Wap,
    const float* __restrict__ bap, const float* __restrict__ Wvp,
    const float* __restrict__ bvp, const float* __restrict__ Wlp,
    const float* __restrict__ blp, const float* __restrict__ bf1,
    const float* __restrict__ bfp1, const float* __restrict__ bng,
    const float* __restrict__ rm1, const float* __restrict__ rm2,
    float* __restrict__ out) {
    extern __shared__ __align__(16) float smem[];
    float* sW_ = smem;
    float* sGT = smem + OFF_GT;
    float* sMxd = smem + OFF_MXD;
    float* sM2yd = smem + OFF_M2YD;
    float* sMzd = smem + OFF_MZD;

    const int tid = threadIdx.x;
    const int row0 = blockIdx.x * 64;
    const int r = tid >> 2, q = tid & 3;  // matvec mapping
    const int r0 = (tid >> 3) * 2;        // GEMM rows (2 per thread)
    const int g = tid & 7;                // GEMM col group
    const int c0 = g * 8;

    // ---- P0: Wfp1T -> sW; gated mean -> sGT[64..127]; fusion-2 factors ----
    copy16(sW_, g_WT[0], tid);
#pragma unroll
    for (int it = 0; it < 16; it++) {
        int i = tid + it * 256;
        int rr = i >> 6, cc = i & 63;
        sGT[(64 + cc) * 68 + rr] =
            gatef_(__ldg(mean + (row0 + rr) * 64 + cc), __ldg(rm1 + 64 + cc));
    }
    matvec_pool(pa, pv, pl, row0 + r, sMxd, sM2yd, sMzd, Wap, bap, Wvp, bvp,
                Wlp, blp, r, q);
    __syncthreads();

    // ---- P1: GEMM1 (K=256) -> gate -> sGT[0..63] ----
    {
        ull acc[2][4] = {};
        gemm_fuse(sW_, sMxd, sM2yd, sMzd, r0, g, acc);
#pragma unroll
        for (int j = 0; j < 4; j++) {
            int ca = c0 + 2 * j, cb = ca + 1;
            float bca = __ldg(bfp1 + ca), bcb = __ldg(bfp1 + cb);
            float rca = __ldg(rm1 + ca), rcb = __ldg(rm1 + cb);
            float2 pr0 = unpk_(acc[0][j]);  // (col ca, col cb) of row r0
            float2 pr1 = unpk_(acc[1][j]);  // of row r0+1
            *reinterpret_cast<float2*>(sGT + ca * 68 + r0) =
                make_float2(gatef_(leakyf_(pr0.x + bca), rca),
                            gatef_(leakyf_(pr1.x + bca), rca));
            *reinterpret_cast<float2*>(sGT + cb * 68 + r0) =
                make_float2(gatef_(leakyf_(pr0.y + bcb), rcb),
                            gatef_(leakyf_(pr1.y + bcb), rcb));
        }
    }
    __syncthreads();

    // ---- P2: WngT -> sW[0:8192]; fusion-1 factors ----
    copy8(sW_, g_WngT, tid);
    matvec_pool(a, v, l, row0 + r, sMxd, sM2yd, sMzd, Wa, ba, Wv, bv, Wl, bl,
                r, q);
    __syncthreads();

    // ---- P3: GEMM2 (K=128) -> out[:,0:64]; prefetch Wf1T upper half ----
    {
        ull acc2[2][4] = {};
#pragma unroll 4
        for (int k = 0; k < 128; k++) {
            ull fp = *reinterpret_cast<const ull*>(sGT + k * 68 + r0);
            float2 fv = unpk_(fp);
            ull f0 = dup2_(fv.x), f1 = dup2_(fv.y);
            ulonglong2 wA =
                *reinterpret_cast<const ulonglong2*>(sW_ + k * 64 + c0);
            ulonglong2 wB =
                *reinterpret_cast<const ulonglong2*>(sW_ + k * 64 + c0 + 4);
            ffma2_(acc2[0][0], f0, wA.x); ffma2_(acc2[0][1], f0, wA.y);
            ffma2_(acc2[0][2], f0, wB.x); ffma2_(acc2[0][3], f0, wB.y);
            ffma2_(acc2[1][0], f1, wA.x); ffma2_(acc2[1][1], f1, wA.y);
            ffma2_(acc2[1][2], f1, wB.x); ffma2_(acc2[1][3], f1, wB.y);
        }
        float4 bbA = __ldg(reinterpret_cast<const float4*>(bng + c0));
        float4 bbB = __ldg(reinterpret_cast<const float4*>(bng + c0 + 4));
        float4 rmA = __ldg(reinterpret_cast<const float4*>(rm2 + c0));
        float4 rmB = __ldg(reinterpret_cast<const float4*>(rm2 + c0 + 4));
#pragma unroll
        for (int i = 0; i < 2; i++) {
            float2 p0 = unpk_(acc2[i][0]), p1 = unpk_(acc2[i][1]);
            float2 p2 = unpk_(acc2[i][2]), p3 = unpk_(acc2[i][3]);
            float* orow = out + (row0 + r0 + i) * 128 + c0;
            *reinterpret_cast<float4*>(orow) =
                make_float4(gatef_(p0.x + bbA.x, rmA.x),
                            gatef_(p0.y + bbA.y, rmA.y),
                            gatef_(p1.x + bbA.z, rmA.z),
                            gatef_(p1.y + bbA.w, rmA.w));
            *reinterpret_cast<float4*>(orow + 4) =
                make_float4(gatef_(p2.x + bbB.x, rmB.x),
                            gatef_(p2.y + bbB.y, rmB.y),
                            gatef_(p3.x + bbB.z, rmB.z),
                            gatef_(p3.y + bbB.w, rmB.w));
        }
    }
    copy8(sW_ + 8192, g_WT[1] + 8192, tid);  // upper half of Wf1T
    __syncthreads();

    // ---- P4: lower half of Wf1T -> sW[0:8192] ----
    copy8(sW_, g_WT[1], tid);
    __syncthreads();

    // ---- P5: GEMM3 (K=256) -> out[:,64:128] ----
    {
        ull acc[2][4] = {};
        gemm_fuse(sW_, sMxd, sM2yd, sMzd, r0, g, acc);
        float4 bbA = __ldg(reinterpret_cast<const float4*>(bf1 + c0));
        float4 bbB = __ldg(reinterpret_cast<const float4*>(bf1 + c0 + 4));
        float4 rmA = __ldg(reinterpret_cast<const float4*>(rm2 + 64 + c0));
        float4 rmB = __ldg(reinterpret_cast<const float4*>(rm2 + 64 + c0 + 4));
#pragma unroll
        for (int i = 0; i < 2; i++) {
            float2 p0 = unpk_(acc[i][0]), p1 = unpk_(acc[i][1]);
            float2 p2 = unpk_(acc[i][2]), p3 = unpk_(acc[i][3]);
            float* orow = out + (row0 + r0 + i) * 128 + 64 + c0;
            *reinterpret_cast<float4*>(orow) =
                make_float4(gatef_(leakyf_(p0.x + bbA.x), rmA.x),
                            gatef_(leakyf_(p0.y + bbA.y), rmA.y),
                            gatef_(leakyf_(p1.x + bbA.z), rmA.z),
                            gatef_(leakyf_(p1.y + bbA.w), rmA.w));
            *reinterpret_cast<float4*>(orow + 4) =
                make_float4(gatef_(leakyf_(p2.x + bbB.x), rmB.x),
                            gatef_(leakyf_(p2.y + bbB.y), rmB.y),
                            gatef_(leakyf_(p3.x + bbB.z), rmB.z),
                            gatef_(leakyf_(p3.y + bbB.w), rmB.w));
        }
    }
}

extern "C" void kernel_launch(void* const* d_in, const int* in_sizes, int n_in,
                              void* d_out, int out_size) {
    const float* a    = (const float*)d_in[0];
    const float* v    = (const float*)d_in[1];
    const float* l    = (const float*)d_in[2];
    const float* pa   = (const float*)d_in[3];
    const float* pv   = (const float*)d_in[4];
    const float* pl   = (const float*)d_in[5];
    const float* mean = (const float*)d_in[6];
    const float* Wa   = (const float*)d_in[7];
    const float* ba   = (const float*)d_in[8];
    const float* Wv   = (const float*)d_in[9];
    const float* bv   = (const float*)d_in[10];
    const float* Wl   = (const float*)d_in[11];
    const float* bl   = (const float*)d_in[12];
    const float* Wap  = (const float*)d_in[13];
    const float* bap  = (const float*)d_in[14];
    const float* Wvp  = (const float*)d_in[15];
    const float* bvp  = (const float*)d_in[16];
    const float* Wlp  = (const float*)d_in[17];
    const float* blp  = (const float*)d_in[18];
    const float* Wf1  = (const float*)d_in[19];
    const float* bf1  = (const float*)d_in[20];
    const float* Wfp1 = (const float*)d_in[21];
    const float* bfp1 = (const float*)d_in[22];
    const float* Wng  = (const float*)d_in[23];
    const float* bng  = (const float*)d_in[24];
    const float* rm1  = (const float*)d_in[25];
    const float* rm2  = (const float*)d_in[26];

    int nrows = in_sizes[0] / 64;
    static int smem_set = 0;
    if (!smem_set) {
        cudaFuncSetAttribute(fusion_main,
                             cudaFuncAttributeMaxDynamicSharedMemorySize,
                             SMEM_FLOATS * 4);
        smem_set = 1;
    }

    setup_kernel<<<64, 256>>>(Wfp1, Wf1, Wng);
    fusion_main<<<nrows / 64, 256, SMEM_FLOATS * 4>>>(
        a, v, l, pa, pv, pl, mean, Wa, ba, Wv, bv, Wl, bl, Wap, bap, Wvp, bvp,
        Wlp, blp, bf1, bfp1, bng, rm1, rm2, (float*)d_out);
}

// round 10
// speedup vs baseline: 1.5009x; 1.5009x over previous
#include <cuda_runtime.h>

typedef unsigned long long ull;

// Weights in global, built per replay by setup_kernel.
// g_WT[i]: interleaved transposed fusion weights:
//   d = k*64 + h*32 + g*4 + e  <->  c = g*8 + h*4 + e   (h<2, e<4, g<8)
// g_WngT: plain transposed [k][c].
__device__ float g_WT[2][256 * 64];
__device__ float g_WngT[128 * 64];

__global__ void setup_kernel(const float* __restrict__ Wfp1,
                             const float* __restrict__ Wf1,
                             const float* __restrict__ Wng) {
    int tid = blockIdx.x * blockDim.x + threadIdx.x;
    int stride = gridDim.x * blockDim.x;
    for (int i = tid; i < 64 * 256; i += stride) {
        int c = i >> 8, k = i & 255;
        int g = c >> 3, h = (c >> 2) & 1, e = c & 3;
        g_WT[0][k * 64 + h * 32 + g * 4 + e] = Wfp1[i];
        g_WT[1][k * 64 + h * 32 + g * 4 + e] = Wf1[i];
    }
    for (int i = tid; i < 64 * 128; i += stride) {
        int c = i >> 7, k = i & 127;
        g_WngT[k * 64 + c] = Wng[i];
    }
}

__device__ __forceinline__ float sigmoidf_(float x) {
    return __fdividef(1.0f, 1.0f + __expf(-x));
}
__device__ __forceinline__ float gatef_(float x, float rm) {
    return x * sigmoidf_(fabsf(x - rm));
}
__device__ __forceinline__ float leakyf_(float x) {
    return x > 0.0f ? x : 0.01f * x;
}
__device__ __forceinline__ void ffma2_(ull& d, ull a, ull b) {
    asm("fma.rn.f32x2 %0, %1, %2, %0;" : "+l"(d) : "l"(a), "l"(b));
}
__device__ __forceinline__ ull fmul2_(ull a, ull b) {
    ull r;
    asm("mul.rn.f32x2 %0, %1, %2;" : "=l"(r) : "l"(a), "l"(b));
    return r;
}
__device__ __forceinline__ ull dup2_(float x) {
    ull r;
    unsigned u = __float_as_uint(x);
    asm("mov.b64 %0, {%1, %1};" : "=l"(r) : "r"(u));
    return r;
}
__device__ __forceinline__ float2 unpk_(ull v) {
    float2 r;
    asm("mov.b64 {%0, %1}, %2;" : "=f"(r.x), "=f"(r.y) : "l"(v));
    return r;
}
__device__ __forceinline__ void st_dup2(float* p, float v) {
    *reinterpret_cast<float2*>(p) = make_float2(v, v);
}

// Copy 8192 floats global -> smem, coalesced.
__device__ __forceinline__ void copy8(float* __restrict__ dst,
                                      const float* __restrict__ src, int tid) {
    const float4* s = reinterpret_cast<const float4*>(src);
    float4* d = reinterpret_cast<float4*>(dst);
#pragma unroll
    for (int i = 0; i < 8; i++) d[tid + i * 256] = s[tid + i * 256];
}

// Stage one modality (64 rows x 64 floats) into sIn[64][68], coalesced.
__device__ __forceinline__ void stage_in(float* __restrict__ sIn,
                                         const float* __restrict__ src,
                                         int row0, int tid) {
    const float4* s =
        reinterpret_cast<const float4*>(src + (size_t)row0 * 64);
#pragma unroll
    for (int it = 0; it < 4; it++) {
        int i = tid + it * 256;
        *reinterpret_cast<float4*>(sIn + (i >> 4) * 68 + (i & 15) * 4) = s[i];
    }
}

// 4-output matvec + sigmoid from staged smem input.
// Warp-level mapping: q selects output quad (warp-uniform weight loads),
// lane selects row rloc. W loads: all lanes share address -> 1 L1 line.
__device__ __forceinline__ void mv4s(const float* __restrict__ sIn,
                                     const float* __restrict__ W,
                                     const float* __restrict__ b, int rloc,
                                     int q, float h[4]) {
    ull acc[4] = {0, 0, 0, 0};
    const float* xr = sIn + rloc * 68;
#pragma unroll 4
    for (int k = 0; k < 64; k += 4) {
        ulonglong2 xv = *reinterpret_cast<const ulonglong2*>(xr + k);
#pragma unroll
        for (int j = 0; j < 4; j++) {
            ulonglong2 w = __ldg(reinterpret_cast<const ulonglong2*>(
                W + (q * 4 + j) * 64 + k));
            ffma2_(acc[j], xv.x, w.x);
            ffma2_(acc[j], xv.y, w.y);
        }
    }
#pragma unroll
    for (int j = 0; j < 4; j++) {
        float2 p = unpk_(acc[j]);
        h[j] = sigmoidf_(p.x + p.y + __ldg(b + q * 4 + j));
    }
}

// Fusion GEMM over one k-half (128 k = 4 ix values), 4 rows x 8 cols/thread.
// F[k = (ix*4+iy)*8 + t][row] = mx[ix]*m2y[iy]*mz[t], weights interleaved.
__device__ __forceinline__ void gemm_half(
    const float* __restrict__ sW_, const float* __restrict__ sMxd,
    const float* __restrict__ sM2yd, const float* __restrict__ sMzd, int r0,
    int g, int ix0, ull acc[4][4]) {
    ull my[4][4];
#pragma unroll
    for (int iy = 0; iy < 4; iy++) {
        ulonglong2 ya =
            *reinterpret_cast<const ulonglong2*>(sM2yd + iy * 128 + 2 * r0);
        ulonglong2 yb = *reinterpret_cast<const ulonglong2*>(sM2yd + iy * 128 +
                                                             2 * r0 + 4);
        my[iy][0] = ya.x; my[iy][1] = ya.y;
        my[iy][2] = yb.x; my[iy][3] = yb.y;
    }
    const float* zbase = sMzd + 2 * r0;
#pragma unroll 1
    for (int ixl = 0; ixl < 4; ixl++) {
        int ix = ix0 + ixl;
        ulonglong2 ma =
            *reinterpret_cast<const ulonglong2*>(sMxd + ix * 128 + 2 * r0);
        ulonglong2 mb = *reinterpret_cast<const ulonglong2*>(sMxd + ix * 128 +
                                                             2 * r0 + 4);
#pragma unroll
        for (int iy = 0; iy < 4; iy++) {
            ull P0 = fmul2_(ma.x, my[iy][0]);
            ull P1 = fmul2_(ma.y, my[iy][1]);
            ull P2 = fmul2_(mb.x, my[iy][2]);
            ull P3 = fmul2_(mb.y, my[iy][3]);
            const float* wrow = sW_ + (ixl * 4 + iy) * 512 + g * 4;
#pragma unroll
            for (int t = 0; t < 8; t++) {
                ulonglong2 za =
                    *reinterpret_cast<const ulonglong2*>(zbase + t * 128);
                ulonglong2 zb =
                    *reinterpret_cast<const ulonglong2*>(zbase + t * 128 + 4);
                ulonglong2 w0 =
                    *reinterpret_cast<const ulonglong2*>(wrow + t * 64);
                ulonglong2 w1 =
                    *reinterpret_cast<const ulonglong2*>(wrow + t * 64 + 32);
                ull f0 = fmul2_(P0, za.x);
                ull f1 = fmul2_(P1, za.y);
                ull f2 = fmul2_(P2, zb.x);
                ull f3 = fmul2_(P3, zb.y);
                ffma2_(acc[0][0], f0, w0.x); ffma2_(acc[0][1], f0, w0.y);
                ffma2_(acc[0][2], f0, w1.x); ffma2_(acc[0][3], f0, w1.y);
                ffma2_(acc[1][0], f1, w0.x); ffma2_(acc[1][1], f1, w0.y);
                ffma2_(acc[1][2], f1, w1.x); ffma2_(acc[1][3], f1, w1.y);
                ffma2_(acc[2][0], f2, w0.x); ffma2_(acc[2][1], f2, w0.y);
                ffma2_(acc[2][2], f2, w1.x); ffma2_(acc[2][3], f2, w1.y);
                ffma2_(acc[3][0], f3, w0.x); ffma2_(acc[3][1], f3, w0.y);
                ffma2_(acc[3][2], f3, w1.x); ffma2_(acc[3][3], f3, w1.y);
            }
        }
    }
}

// Shared layout (floats):
//  sW    @ 0     : 8192   (one 32KB weight half / WngT)
//  sGT   @ 8192  : 8704   ([128 k][68], entry k*68 + r)
//  sMxd  @ 16896 : 1024   ([8][128] dup'd)
//  sM2yd @ 17920 : 512    ([4][128])
//  sMzd  @ 18432 : 1024   ([8][128])
//  sIn   @ 19456 : 4352   ([64][68] staged inputs)
//  total 23808 floats = 95232 B -> 2 CTAs/SM
#define OFF_GT 8192
#define OFF_MXD 16896
#define OFF_M2YD 17920
#define OFF_MZD 18432
#define OFF_IN 19456
#define SMEM_FLOATS 23808

__global__ void __launch_bounds__(256, 2) fusion_main(
    const float* __restrict__ a, const float* __restrict__ v,
    const float* __restrict__ l, const float* __restrict__ pa,
    const float* __restrict__ pv, const float* __restrict__ pl,
    const float* __restrict__ mean, const float* __restrict__ Wa,
    const float* __restrict__ ba, const float* __restrict__ Wv,
    const float* __restrict__ bv, const float* __restrict__ Wl,
    const float* __restrict__ bl, const float* __restrict__ Wap,
    const float* __restrict__ bap, const float* __restrict__ Wvp,
    const float* __restrict__ bvp, const float* __restrict__ Wlp,
    const float* __restrict__ blp, const float* __restrict__ bf1,
    const float* __restrict__ bfp1, const float* __restrict__ bng,
    const float* __restrict__ rm1, const float* __restrict__ rm2,
    float* __restrict__ out) {
    extern __shared__ __align__(16) float smem[];
    float* sW_ = smem;
    float* sGT = smem + OFF_GT;
    float* sMxd = smem + OFF_MXD;
    float* sM2yd = smem + OFF_M2YD;
    float* sMzd = smem + OFF_MZD;
    float* sIn = smem + OFF_IN;

    const int tid = threadIdx.x;
    const int row0 = blockIdx.x * 64;
    const int wid = tid >> 5, lane = tid & 31;
    const int q = wid & 3;                    // matvec output quad
    const int rloc = (wid >> 2) * 32 + lane;  // matvec row
    const int r0 = (tid >> 3) * 4;            // GEMM1/3 rows (tid<128)
    const int g = tid & 7;                    // GEMM1/3 col group
    const int c0 = g * 8;
    float h[4];

    // ---- P0: Wfp1T(A) -> sW; gated mean -> sGT[64..127]; f2 factors ----
    copy8(sW_, g_WT[0], tid);
#pragma unroll
    for (int it = 0; it < 16; it++) {
        int i = tid + it * 256;
        int rr = i >> 6, cc = i & 63;
        sGT[(64 + cc) * 68 + rr] =
            gatef_(__ldg(mean + (row0 + rr) * 64 + cc), __ldg(rm1 + 64 + cc));
    }
    stage_in(sIn, pa, row0, tid);
    __syncthreads();
    mv4s(sIn, Wap, bap, rloc, q, h);
    st_dup2(sMxd + (2 * q) * 128 + 2 * rloc, fmaxf(h[0], h[1]));
    st_dup2(sMxd + (2 * q + 1) * 128 + 2 * rloc, fmaxf(h[2], h[3]));
    __syncthreads();
    stage_in(sIn, pv, row0, tid);
    __syncthreads();
    mv4s(sIn, Wvp, bvp, rloc, q, h);
    st_dup2(sM2yd + q * 128 + 2 * rloc,
            fmaxf(fmaxf(h[0], h[1]), fmaxf(h[2], h[3])));
    __syncthreads();
    stage_in(sIn, pl, row0, tid);
    __syncthreads();
    mv4s(sIn, Wlp, blp, rloc, q, h);
    st_dup2(sMzd + (2 * q) * 128 + 2 * rloc, fmaxf(h[0], h[1]));
    st_dup2(sMzd + (2 * q + 1) * 128 + 2 * rloc, fmaxf(h[2], h[3]));
    __syncthreads();

    // ---- P1: GEMM1 (two k-halves) -> gate -> sGT[0..63] ----
    {
        ull acc[4][4] = {};
        if (tid < 128) gemm_half(sW_, sMxd, sM2yd, sMzd, r0, g, 0, acc);
        __syncthreads();
        copy8(sW_, g_WT[0] + 8192, tid);
        __syncthreads();
        if (tid < 128) {
            gemm_half(sW_, sMxd, sM2yd, sMzd, r0, g, 4, acc);
#pragma unroll
            for (int j = 0; j < 4; j++) {
                int ca = c0 + 2 * j, cb = ca + 1;
                float bca = __ldg(bfp1 + ca), bcb = __ldg(bfp1 + cb);
                float rca = __ldg(rm1 + ca), rcb = __ldg(rm1 + cb);
                float2 p0 = unpk_(acc[0][j]), p1 = unpk_(acc[1][j]);
                float2 p2 = unpk_(acc[2][j]), p3 = unpk_(acc[3][j]);
                *reinterpret_cast<float4*>(sGT + ca * 68 + r0) =
                    make_float4(gatef_(leakyf_(p0.x + bca), rca),
                                gatef_(leakyf_(p1.x + bca), rca),
                                gatef_(leakyf_(p2.x + bca), rca),
                                gatef_(leakyf_(p3.x + bca), rca));
                *reinterpret_cast<float4*>(sGT + cb * 68 + r0) =
                    make_float4(gatef_(leakyf_(p0.y + bcb), rcb),
                                gatef_(leakyf_(p1.y + bcb), rcb),
                                gatef_(leakyf_(p2.y + bcb), rcb),
                                gatef_(leakyf_(p3.y + bcb), rcb));
            }
        }
        __syncthreads();
    }

    // ---- P2: WngT -> sW; fusion-1 factors (staged) ----
    copy8(sW_, g_WngT, tid);
    stage_in(sIn, a, row0, tid);
    __syncthreads();
    mv4s(sIn, Wa, ba, rloc, q, h);
    st_dup2(sMxd + (2 * q) * 128 + 2 * rloc, fmaxf(h[0], h[1]));
    st_dup2(sMxd + (2 * q + 1) * 128 + 2 * rloc, fmaxf(h[2], h[3]));
    __syncthreads();
    stage_in(sIn, v, row0, tid);
    __syncthreads();
    mv4s(sIn, Wv, bv, rloc, q, h);
    st_dup2(sM2yd + q * 128 + 2 * rloc,
            fmaxf(fmaxf(h[0], h[1]), fmaxf(h[2], h[3])));
    __syncthreads();
    stage_in(sIn, l, row0, tid);
    __syncthreads();
    mv4s(sIn, Wl, bl, rloc, q, h);
    st_dup2(sMzd + (2 * q) * 128 + 2 * rloc, fmaxf(h[0], h[1]));
    st_dup2(sMzd + (2 * q + 1) * 128 + 2 * rloc, fmaxf(h[2], h[3]));
    __syncthreads();

    // ---- P3: GEMM2 (K=128, 4r x 4c, all 256 threads) -> out[:,0:64] ----
    {
        const int r2 = (tid >> 4) * 4, c2 = (tid & 15) * 4;
        ull acc2[4][2] = {};
#pragma unroll 4
        for (int k = 0; k < 128; k++) {
            float4 fv = *reinterpret_cast<const float4*>(sGT + k * 68 + r2);
            ulonglong2 w =
                *reinterpret_cast<const ulonglong2*>(sW_ + k * 64 + c2);
            ull f0 = dup2_(fv.x), f1 = dup2_(fv.y);
            ull f2 = dup2_(fv.z), f3 = dup2_(fv.w);
            ffma2_(acc2[0][0], f0, w.x); ffma2_(acc2[0][1], f0, w.y);
            ffma2_(acc2[1][0], f1, w.x); ffma2_(acc2[1][1], f1, w.y);
            ffma2_(acc2[2][0], f2, w.x); ffma2_(acc2[2][1], f2, w.y);
            ffma2_(acc2[3][0], f3, w.x); ffma2_(acc2[3][1], f3, w.y);
        }
        float4 bb = __ldg(reinterpret_cast<const float4*>(bng + c2));
        float4 rr2 = __ldg(reinterpret_cast<const float4*>(rm2 + c2));
#pragma unroll
        for (int i = 0; i < 4; i++) {
            float2 pA = unpk_(acc2[i][0]), pB = unpk_(acc2[i][1]);
            *reinterpret_cast<float4*>(out + (row0 + r2 + i) * 128 + c2) =
                make_float4(gatef_(pA.x + bb.x, rr2.x),
                            gatef_(pA.y + bb.y, rr2.y),
                            gatef_(pB.x + bb.z, rr2.z),
                            gatef_(pB.y + bb.w, rr2.w));
        }
    }
    __syncthreads();

    // ---- P4: GEMM3 (two k-halves) -> out[:,64:128] ----
    copy8(sW_, g_WT[1], tid);
    __syncthreads();
    {
        ull acc[4][4] = {};
        if (tid < 128) gemm_half(sW_, sMxd, sM2yd, sMzd, r0, g, 0, acc);
        __syncthreads();
        copy8(sW_, g_WT[1] + 8192, tid);
        __syncthreads();
        if (tid < 128) {
            gemm_half(sW_, sMxd, sM2yd, sMzd, r0, g, 4, acc);
            float4 bbA = __ldg(reinterpret_cast<const float4*>(bf1 + c0));
            float4 bbB = __ldg(reinterpret_cast<const float4*>(bf1 + c0 + 4));
            float4 rmA = __ldg(reinterpret_cast<const float4*>(rm2 + 64 + c0));
            float4 rmB =
                __ldg(reinterpret_cast<const float4*>(rm2 + 64 + c0 + 4));
#pragma unroll
            for (int i = 0; i < 4; i++) {
                float2 p0 = unpk_(acc[i][0]), p1 = unpk_(acc[i][1]);
                float2 p2 = unpk_(acc[i][2]), p3 = unpk_(acc[i][3]);
                float* orow = out + (row0 + r0 + i) * 128 + 64 + c0;
                *reinterpret_cast<float4*>(orow) =
                    make_float4(gatef_(leakyf_(p0.x + bbA.x), rmA.x),
                                gatef_(leakyf_(p0.y + bbA.y), rmA.y),
                                gatef_(leakyf_(p1.x + bbA.z), rmA.z),
                                gatef_(leakyf_(p1.y + bbA.w), rmA.w));
                *reinterpret_cast<float4*>(orow + 4) =
                    make_float4(gatef_(leakyf_(p2.x + bbB.x), rmB.x),
                                gatef_(leakyf_(p2.y + bbB.y), rmB.y),
                                gatef_(leakyf_(p3.x + bbB.z), rmB.z),
                                gatef_(leakyf_(p3.y + bbB.w), rmB.w));
            }
        }
    }
}

extern "C" void kernel_launch(void* const* d_in, const int* in_sizes, int n_in,
                              void* d_out, int out_size) {
    const float* a    = (const float*)d_in[0];
    const float* v    = (const float*)d_in[1];
    const float* l    = (const float*)d_in[2];
    const float* pa   = (const float*)d_in[3];
    const float* pv   = (const float*)d_in[4];
    const float* pl   = (const float*)d_in[5];
    const float* mean = (const float*)d_in[6];
    const float* Wa   = (const float*)d_in[7];
    const float* ba   = (const float*)d_in[8];
    const float* Wv   = (const float*)d_in[9];
    const float* bv   = (const float*)d_in[10];
    const float* Wl   = (const float*)d_in[11];
    const float* bl   = (const float*)d_in[12];
    const float* Wap  = (const float*)d_in[13];
    const float* bap  = (const float*)d_in[14];
    const float* Wvp  = (const float*)d_in[15];
    const float* bvp  = (const float*)d_in[16];
    const float* Wlp  = (const float*)d_in[17];
    const float* blp  = (const float*)d_in[18];
    const float* Wf1  = (const float*)d_in[19];
    const float* bf1  = (const float*)d_in[20];
    const float* Wfp1 = (const float*)d_in[21];
    const float* bfp1 = (const float*)d_in[22];
    const float* Wng  = (const float*)d_in[23];
    const float* bng  = (const float*)d_in[24];
    const float* rm1  = (const float*)d_in[25];
    const float* rm2  = (const float*)d_in[26];

    int nrows = in_sizes[0] / 64;
    static int smem_set = 0;
    if (!smem_set) {
        cudaFuncSetAttribute(fusion_main,
                             cudaFuncAttributeMaxDynamicSharedMemorySize,
                             SMEM_FLOATS * 4);
        smem_set = 1;
    }

    setup_kernel<<<64, 256>>>(Wfp1, Wf1, Wng);
    fusion_main<<<nrows / 64, 256, SMEM_FLOATS * 4>>>(
        a, v, l, pa, pv, pl, mean, Wa, ba, Wv, bv, Wl, bl, Wap, bap, Wvp, bvp,
        Wlp, blp, bf1, bfp1, bng, rm1, rm2, (float*)d_out);
}

// round 11
// speedup vs baseline: 1.6543x; 1.1022x over previous
#include <cuda_runtime.h>

typedef unsigned long long ull;

// Weights in global, built per replay by setup_kernel.
// g_WT[i]: interleaved transposed fusion weights:
//   d = k*64 + h*32 + g*4 + e  <->  c = g*8 + h*4 + e   (h<2, e<4, g<8)
// g_WngT: plain transposed [k][c].
__device__ float g_WT[2][256 * 64];
__device__ float g_WngT[128 * 64];

__global__ void setup_kernel(const float* __restrict__ Wfp1,
                             const float* __restrict__ Wf1,
                             const float* __restrict__ Wng) {
    int tid = blockIdx.x * blockDim.x + threadIdx.x;
    int stride = gridDim.x * blockDim.x;
    for (int i = tid; i < 64 * 256; i += stride) {
        int c = i >> 8, k = i & 255;
        int g = c >> 3, h = (c >> 2) & 1, e = c & 3;
        g_WT[0][k * 64 + h * 32 + g * 4 + e] = Wfp1[i];
        g_WT[1][k * 64 + h * 32 + g * 4 + e] = Wf1[i];
    }
    for (int i = tid; i < 64 * 128; i += stride) {
        int c = i >> 7, k = i & 127;
        g_WngT[k * 64 + c] = Wng[i];
    }
}

__device__ __forceinline__ float sigmoidf_(float x) {
    return __fdividef(1.0f, 1.0f + __expf(-x));
}
__device__ __forceinline__ float gatef_(float x, float rm) {
    return x * sigmoidf_(fabsf(x - rm));
}
__device__ __forceinline__ float leakyf_(float x) {
    return x > 0.0f ? x : 0.01f * x;
}
__device__ __forceinline__ void ffma2_(ull& d, ull a, ull b) {
    asm("fma.rn.f32x2 %0, %1, %2, %0;" : "+l"(d) : "l"(a), "l"(b));
}
__device__ __forceinline__ ull fmul2_(ull a, ull b) {
    ull r;
    asm("mul.rn.f32x2 %0, %1, %2;" : "=l"(r) : "l"(a), "l"(b));
    return r;
}
__device__ __forceinline__ ull dup2_(float x) {
    ull r;
    unsigned u = __float_as_uint(x);
    asm("mov.b64 %0, {%1, %1};" : "=l"(r) : "r"(u));
    return r;
}
__device__ __forceinline__ float2 unpk_(ull v) {
    float2 r;
    asm("mov.b64 {%0, %1}, %2;" : "=f"(r.x), "=f"(r.y) : "l"(v));
    return r;
}
__device__ __forceinline__ void st_dup2(float* p, float v) {
    *reinterpret_cast<float2*>(p) = make_float2(v, v);
}

// Copy 8192 floats global -> smem, coalesced.
__device__ __forceinline__ void copy8(float* __restrict__ dst,
                                      const float* __restrict__ src, int tid) {
    const float4* s = reinterpret_cast<const float4*>(src);
    float4* d = reinterpret_cast<float4*>(dst);
#pragma unroll
    for (int i = 0; i < 8; i++) d[tid + i * 256] = s[tid + i * 256];
}

// Stage one modality (64 rows x 64 floats) into sIn[64][68], coalesced.
__device__ __forceinline__ void stage_in(float* __restrict__ sIn,
                                         const float* __restrict__ src,
                                         int row0, int tid) {
    const float4* s =
        reinterpret_cast<const float4*>(src + (size_t)row0 * 64);
#pragma unroll
    for (int it = 0; it < 4; it++) {
        int i = tid + it * 256;
        *reinterpret_cast<float4*>(sIn + (i >> 4) * 68 + (i & 15) * 4) = s[i];
    }
}

// 4-output matvec + sigmoid from staged smem input.
// Warp-level mapping: q selects output quad (warp-uniform weight loads),
// lane selects row rloc. W loads: all lanes share address -> 1 L1 line.
__device__ __forceinline__ void mv4s(const float* __restrict__ sIn,
                                     const float* __restrict__ W,
                                     const float* __restrict__ b, int rloc,
                                     int q, float h[4]) {
    ull acc[4] = {0, 0, 0, 0};
    const float* xr = sIn + rloc * 68;
#pragma unroll 4
    for (int k = 0; k < 64; k += 4) {
        ulonglong2 xv = *reinterpret_cast<const ulonglong2*>(xr + k);
#pragma unroll
        for (int j = 0; j < 4; j++) {
            ulonglong2 w = __ldg(reinterpret_cast<const ulonglong2*>(
                W + (q * 4 + j) * 64 + k));
            ffma2_(acc[j], xv.x, w.x);
            ffma2_(acc[j], xv.y, w.y);
        }
    }
#pragma unroll
    for (int j = 0; j < 4; j++) {
        float2 p = unpk_(acc[j]);
        h[j] = sigmoidf_(p.x + p.y + __ldg(b + q * 4 + j));
    }
}

// Fusion GEMM over one k-half (128 k = 4 ix values), 2 rows x 8 cols/thread,
// all 256 threads active. F[k=(ix*4+iy)*8+t][row] = mx[ix]*m2y[iy]*mz[t].
// mz2/my2 factor tables held in registers across the whole half.
__device__ __forceinline__ void gemm_half2(
    const float* __restrict__ sW_, const float* __restrict__ sMxd,
    const float* __restrict__ sM2yd, const float* __restrict__ sMzd, int r0,
    int g, int ix0, ull acc[2][4]) {
    ull mz2[2][8];
#pragma unroll
    for (int t = 0; t < 8; t++) {
        ulonglong2 m =
            *reinterpret_cast<const ulonglong2*>(sMzd + t * 128 + 2 * r0);
        mz2[0][t] = m.x;
        mz2[1][t] = m.y;
    }
    ull my2[2][4];
#pragma unroll
    for (int iy = 0; iy < 4; iy++) {
        ulonglong2 y =
            *reinterpret_cast<const ulonglong2*>(sM2yd + iy * 128 + 2 * r0);
        my2[0][iy] = y.x;
        my2[1][iy] = y.y;
    }
#pragma unroll 1
    for (int ixl = 0; ixl < 4; ixl++) {
        ulonglong2 ma = *reinterpret_cast<const ulonglong2*>(
            sMxd + (ix0 + ixl) * 128 + 2 * r0);
#pragma unroll
        for (int iy = 0; iy < 4; iy++) {
            ull P0 = fmul2_(ma.x, my2[0][iy]);
            ull P1 = fmul2_(ma.y, my2[1][iy]);
            const float* wrow = sW_ + (ixl * 4 + iy) * 512 + g * 4;
#pragma unroll
            for (int t = 0; t < 8; t++) {
                ulonglong2 w0 =
                    *reinterpret_cast<const ulonglong2*>(wrow + t * 64);
                ulonglong2 w1 =
                    *reinterpret_cast<const ulonglong2*>(wrow + t * 64 + 32);
                ull f0 = fmul2_(P0, mz2[0][t]);
                ull f1 = fmul2_(P1, mz2[1][t]);
                ffma2_(acc[0][0], f0, w0.x); ffma2_(acc[0][1], f0, w0.y);
                ffma2_(acc[0][2], f0, w1.x); ffma2_(acc[0][3], f0, w1.y);
                ffma2_(acc[1][0], f1, w0.x); ffma2_(acc[1][1], f1, w0.y);
                ffma2_(acc[1][2], f1, w1.x); ffma2_(acc[1][3], f1, w1.y);
            }
        }
    }
}

// Shared layout (floats):
//  sW    @ 0     : 8192   (one 32KB weight half / WngT)
//  sGT   @ 8192  : 8704   ([128 k][68], entry k*68 + r)
//  sMxd  @ 16896 : 1024   ([8][128] dup'd)
//  sM2yd @ 17920 : 512    ([4][128])
//  sMzd  @ 18432 : 1024   ([8][128])
//  sIn   @ 19456 : 4352   ([64][68] staged inputs)
//  total 23808 floats = 95232 B -> 2 CTAs/SM
#define OFF_GT 8192
#define OFF_MXD 16896
#define OFF_M2YD 17920
#define OFF_MZD 18432
#define OFF_IN 19456
#define SMEM_FLOATS 23808

__global__ void __launch_bounds__(256, 2) fusion_main(
    const float* __restrict__ a, const float* __restrict__ v,
    const float* __restrict__ l, const float* __restrict__ pa,
    const float* __restrict__ pv, const float* __restrict__ pl,
    const float* __restrict__ mean, const float* __restrict__ Wa,
    const float* __restrict__ ba, const float* __restrict__ Wv,
    const float* __restrict__ bv, const float* __restrict__ Wl,
    const float* __restrict__ bl, const float* __restrict__ Wap,
    const float* __restrict__ bap, const float* __restrict__ Wvp,
    const float* __restrict__ bvp, const float* __restrict__ Wlp,
    const float* __restrict__ blp, const float* __restrict__ bf1,
    const float* __restrict__ bfp1, const float* __restrict__ bng,
    const float* __restrict__ rm1, const float* __restrict__ rm2,
    float* __restrict__ out) {
    extern __shared__ __align__(16) float smem[];
    float* sW_ = smem;
    float* sGT = smem + OFF_GT;
    float* sMxd = smem + OFF_MXD;
    float* sM2yd = smem + OFF_M2YD;
    float* sMzd = smem + OFF_MZD;
    float* sIn = smem + OFF_IN;

    const int tid = threadIdx.x;
    const int row0 = blockIdx.x * 64;
    const int wid = tid >> 5, lane = tid & 31;
    const int q = wid & 3;                    // matvec output quad
    const int rloc = (wid >> 2) * 32 + lane;  // matvec row
    const int r0 = (tid >> 3) * 2;            // GEMM1/3 rows (2 per thread)
    const int g = tid & 7;                    // GEMM1/3 col group
    const int c0 = g * 8;
    float h[4];

    // ---- P0: Wfp1T(A) -> sW; gated mean -> sGT[64..127]; f2 factors ----
    copy8(sW_, g_WT[0], tid);
#pragma unroll
    for (int it = 0; it < 16; it++) {
        int i = tid + it * 256;
        int rr = i >> 6, cc = i & 63;
        sGT[(64 + cc) * 68 + rr] =
            gatef_(__ldg(mean + (row0 + rr) * 64 + cc), __ldg(rm1 + 64 + cc));
    }
    stage_in(sIn, pa, row0, tid);
    __syncthreads();
    mv4s(sIn, Wap, bap, rloc, q, h);
    st_dup2(sMxd + (2 * q) * 128 + 2 * rloc, fmaxf(h[0], h[1]));
    st_dup2(sMxd + (2 * q + 1) * 128 + 2 * rloc, fmaxf(h[2], h[3]));
    __syncthreads();
    stage_in(sIn, pv, row0, tid);
    __syncthreads();
    mv4s(sIn, Wvp, bvp, rloc, q, h);
    st_dup2(sM2yd + q * 128 + 2 * rloc,
            fmaxf(fmaxf(h[0], h[1]), fmaxf(h[2], h[3])));
    __syncthreads();
    stage_in(sIn, pl, row0, tid);
    __syncthreads();
    mv4s(sIn, Wlp, blp, rloc, q, h);
    st_dup2(sMzd + (2 * q) * 128 + 2 * rloc, fmaxf(h[0], h[1]));
    st_dup2(sMzd + (2 * q + 1) * 128 + 2 * rloc, fmaxf(h[2], h[3]));
    __syncthreads();

    // ---- P1: GEMM1 (two k-halves, all 256 threads) -> gate -> sGT[0..63] ----
    {
        ull acc[2][4] = {};
        gemm_half2(sW_, sMxd, sM2yd, sMzd, r0, g, 0, acc);
        __syncthreads();
        copy8(sW_, g_WT[0] + 8192, tid);
        __syncthreads();
        gemm_half2(sW_, sMxd, sM2yd, sMzd, r0, g, 4, acc);
#pragma unroll
        for (int j = 0; j < 4; j++) {
            int ca = c0 + 2 * j, cb = ca + 1;
            float bca = __ldg(bfp1 + ca), bcb = __ldg(bfp1 + cb);
            float rca = __ldg(rm1 + ca), rcb = __ldg(rm1 + cb);
            float2 p0 = unpk_(acc[0][j]);  // row r0: cols (ca, cb)
            float2 p1 = unpk_(acc[1][j]);  // row r0+1
            *reinterpret_cast<float2*>(sGT + ca * 68 + r0) =
                make_float2(gatef_(leakyf_(p0.x + bca), rca),
                            gatef_(leakyf_(p1.x + bca), rca));
            *reinterpret_cast<float2*>(sGT + cb * 68 + r0) =
                make_float2(gatef_(leakyf_(p0.y + bcb), rcb),
                            gatef_(leakyf_(p1.y + bcb), rcb));
        }
        __syncthreads();
    }

    // ---- P2: WngT -> sW; fusion-1 factors (staged) ----
    copy8(sW_, g_WngT, tid);
    stage_in(sIn, a, row0, tid);
    __syncthreads();
    mv4s(sIn, Wa, ba, rloc, q, h);
    st_dup2(sMxd + (2 * q) * 128 + 2 * rloc, fmaxf(h[0], h[1]));
    st_dup2(sMxd + (2 * q + 1) * 128 + 2 * rloc, fmaxf(h[2], h[3]));
    __syncthreads();
    stage_in(sIn, v, row0, tid);
    __syncthreads();
    mv4s(sIn, Wv, bv, rloc, q, h);
    st_dup2(sM2yd + q * 128 + 2 * rloc,
            fmaxf(fmaxf(h[0], h[1]), fmaxf(h[2], h[3])));
    __syncthreads();
    stage_in(sIn, l, row0, tid);
    __syncthreads();
    mv4s(sIn, Wl, bl, rloc, q, h);
    st_dup2(sMzd + (2 * q) * 128 + 2 * rloc, fmaxf(h[0], h[1]));
    st_dup2(sMzd + (2 * q + 1) * 128 + 2 * rloc, fmaxf(h[2], h[3]));
    __syncthreads();

    // ---- P3: GEMM2 (K=128, 4r x 4c, all 256 threads) -> out[:,0:64] ----
    {
        const int r2 = (tid >> 4) * 4, c2 = (tid & 15) * 4;
        ull acc2[4][2] = {};
#pragma unroll 4
        for (int k = 0; k < 128; k++) {
            float4 fv = *reinterpret_cast<const float4*>(sGT + k * 68 + r2);
            ulonglong2 w =
                *reinterpret_cast<const ulonglong2*>(sW_ + k * 64 + c2);
            ull f0 = dup2_(fv.x), f1 = dup2_(fv.y);
            ull f2 = dup2_(fv.z), f3 = dup2_(fv.w);
            ffma2_(acc2[0][0], f0, w.x); ffma2_(acc2[0][1], f0, w.y);
            ffma2_(acc2[1][0], f1, w.x); ffma2_(acc2[1][1], f1, w.y);
            ffma2_(acc2[2][0], f2, w.x); ffma2_(acc2[2][1], f2, w.y);
            ffma2_(acc2[3][0], f3, w.x); ffma2_(acc2[3][1], f3, w.y);
        }
        float4 bb = __ldg(reinterpret_cast<const float4*>(bng + c2));
        float4 rr2 = __ldg(reinterpret_cast<const float4*>(rm2 + c2));
#pragma unroll
        for (int i = 0; i < 4; i++) {
            float2 pA = unpk_(acc2[i][0]), pB = unpk_(acc2[i][1]);
            *reinterpret_cast<float4*>(out + (row0 + r2 + i) * 128 + c2) =
                make_float4(gatef_(pA.x + bb.x, rr2.x),
                            gatef_(pA.y + bb.y, rr2.y),
                            gatef_(pB.x + bb.z, rr2.z),
                            gatef_(pB.y + bb.w, rr2.w));
        }
    }
    __syncthreads();

    // ---- P4: GEMM3 (two k-halves, all 256 threads) -> out[:,64:128] ----
    copy8(sW_, g_WT[1], tid);
    __syncthreads();
    {
        ull acc[2][4] = {};
        gemm_half2(sW_, sMxd, sM2yd, sMzd, r0, g, 0, acc);
        __syncthreads();
        copy8(sW_, g_WT[1] + 8192, tid);
        __syncthreads();
        gemm_half2(sW_, sMxd, sM2yd, sMzd, r0, g, 4, acc);
        float4 bbA = __ldg(reinterpret_cast<const float4*>(bf1 + c0));
        float4 bbB = __ldg(reinterpret_cast<const float4*>(bf1 + c0 + 4));
        float4 rmA = __ldg(reinterpret_cast<const float4*>(rm2 + 64 + c0));
        float4 rmB = __ldg(reinterpret_cast<const float4*>(rm2 + 64 + c0 + 4));
#pragma unroll
        for (int i = 0; i < 2; i++) {
            float2 p0 = unpk_(acc[i][0]), p1 = unpk_(acc[i][1]);
            float2 p2 = unpk_(acc[i][2]), p3 = unpk_(acc[i][3]);
            float* orow = out + (row0 + r0 + i) * 128 + 64 + c0;
            *reinterpret_cast<float4*>(orow) =
                make_float4(gatef_(leakyf_(p0.x + bbA.x), rmA.x),
                            gatef_(leakyf_(p0.y + bbA.y), rmA.y),
                            gatef_(leakyf_(p1.x + bbA.z), rmA.z),
                            gatef_(leakyf_(p1.y + bbA.w), rmA.w));
            *reinterpret_cast<float4*>(orow + 4) =
                make_float4(gatef_(leakyf_(p2.x + bbB.x), rmB.x),
                            gatef_(leakyf_(p2.y + bbB.y), rmB.y),
                            gatef_(leakyf_(p3.x + bbB.z), rmB.z),
                            gatef_(leakyf_(p3.y + bbB.w), rmB.w));
        }
    }
}

extern "C" void kernel_launch(void* const* d_in, const int* in_sizes, int n_in,
                              void* d_out, int out_size) {
    const float* a    = (const float*)d_in[0];
    const float* v    = (const float*)d_in[1];
    const float* l    = (const float*)d_in[2];
    const float* pa   = (const float*)d_in[3];
    const float* pv   = (const float*)d_in[4];
    const float* pl   = (const float*)d_in[5];
    const float* mean = (const float*)d_in[6];
    const float* Wa   = (const float*)d_in[7];
    const float* ba   = (const float*)d_in[8];
    const float* Wv   = (const float*)d_in[9];
    const float* bv   = (const float*)d_in[10];
    const float* Wl   = (const float*)d_in[11];
    const float* bl   = (const float*)d_in[12];
    const float* Wap  = (const float*)d_in[13];
    const float* bap  = (const float*)d_in[14];
    const float* Wvp  = (const float*)d_in[15];
    const float* bvp  = (const float*)d_in[16];
    const float* Wlp  = (const float*)d_in[17];
    const float* blp  = (const float*)d_in[18];
    const float* Wf1  = (const float*)d_in[19];
    const float* bf1  = (const float*)d_in[20];
    const float* Wfp1 = (const float*)d_in[21];
    const float* bfp1 = (const float*)d_in[22];
    const float* Wng  = (const float*)d_in[23];
    const float* bng  = (const float*)d_in[24];
    const float* rm1  = (const float*)d_in[25];
    const float* rm2  = (const float*)d_in[26];

    int nrows = in_sizes[0] / 64;
    static int smem_set = 0;
    if (!smem_set) {
        cudaFuncSetAttribute(fusion_main,
                             cudaFuncAttributeMaxDynamicSharedMemorySize,
                             SMEM_FLOATS * 4);
        smem_set = 1;
    }

    setup_kernel<<<64, 256>>>(Wfp1, Wf1, Wng);
    fusion_main<<<nrows / 64, 256, SMEM_FLOATS * 4>>>(
        a, v, l, pa, pv, pl, mean, Wa, ba, Wv, bv, Wl, bl, Wap, bap, Wvp, bvp,
        Wlp, blp, bf1, bfp1, bng, rm1, rm2, (float*)d_out);
}

// round 12
// speedup vs baseline: 1.6969x; 1.0257x over previous
#include <cuda_runtime.h>

typedef unsigned long long ull;

// Weights in global, built per replay by setup_kernel.
// Interleaved transposed layout (fusion weights AND WngT):
//   d = k*64 + h*32 + g*4 + e  <->  c = g*8 + h*4 + e   (h<2, e<4, g<8)
__device__ float g_WT[2][256 * 64];
__device__ float g_WngT[128 * 64];

__global__ void setup_kernel(const float* __restrict__ Wfp1,
                             const float* __restrict__ Wf1,
                             const float* __restrict__ Wng) {
    int tid = blockIdx.x * blockDim.x + threadIdx.x;
    int stride = gridDim.x * blockDim.x;
    for (int i = tid; i < 64 * 256; i += stride) {
        int c = i >> 8, k = i & 255;
        int g = c >> 3, h = (c >> 2) & 1, e = c & 3;
        g_WT[0][k * 64 + h * 32 + g * 4 + e] = Wfp1[i];
        g_WT[1][k * 64 + h * 32 + g * 4 + e] = Wf1[i];
    }
    for (int i = tid; i < 64 * 128; i += stride) {
        int c = i >> 7, k = i & 127;
        int g = c >> 3, h = (c >> 2) & 1, e = c & 3;
        g_WngT[k * 64 + h * 32 + g * 4 + e] = Wng[i];
    }
}

__device__ __forceinline__ float sigmoidf_(float x) {
    return __fdividef(1.0f, 1.0f + __expf(-x));
}
__device__ __forceinline__ float gatef_(float x, float rm) {
    return x * sigmoidf_(fabsf(x - rm));
}
__device__ __forceinline__ float leakyf_(float x) {
    return x > 0.0f ? x : 0.01f * x;
}
__device__ __forceinline__ void ffma2_(ull& d, ull a, ull b) {
    asm("fma.rn.f32x2 %0, %1, %2, %0;" : "+l"(d) : "l"(a), "l"(b));
}
__device__ __forceinline__ ull fmul2_(ull a, ull b) {
    ull r;
    asm("mul.rn.f32x2 %0, %1, %2;" : "=l"(r) : "l"(a), "l"(b));
    return r;
}
__device__ __forceinline__ ull dup2_(float x) {
    ull r;
    unsigned u = __float_as_uint(x);
    asm("mov.b64 %0, {%1, %1};" : "=l"(r) : "r"(u));
    return r;
}
__device__ __forceinline__ float2 unpk_(ull v) {
    float2 r;
    asm("mov.b64 {%0, %1}, %2;" : "=f"(r.x), "=f"(r.y) : "l"(v));
    return r;
}
__device__ __forceinline__ void st_dup2(float* p, float v) {
    *reinterpret_cast<float2*>(p) = make_float2(v, v);
}

// Copy 8192 floats global -> smem, coalesced.
__device__ __forceinline__ void copy8(float* __restrict__ dst,
                                      const float* __restrict__ src, int tid) {
    const float4* s = reinterpret_cast<const float4*>(src);
    float4* d = reinterpret_cast<float4*>(dst);
#pragma unroll
    for (int i = 0; i < 8; i++) d[tid + i * 256] = s[tid + i * 256];
}

// Stage three matvec weight sets (16x64 each) into sMvW[3][1024].
__device__ __forceinline__ void stage_mvw(float* __restrict__ sMvW,
                                          const float* __restrict__ Wx,
                                          const float* __restrict__ Wy,
                                          const float* __restrict__ Wz,
                                          int tid) {
    if (tid < 256) {
        float4* d = reinterpret_cast<float4*>(sMvW);
        d[tid] = reinterpret_cast<const float4*>(Wx)[tid];
        d[256 + tid] = reinterpret_cast<const float4*>(Wy)[tid];
        d[512 + tid] = reinterpret_cast<const float4*>(Wz)[tid];
    }
}

// Stage one modality (64 rows x 64 floats) into sIn[64][68], coalesced.
__device__ __forceinline__ void stage_in(float* __restrict__ sIn,
                                         const float* __restrict__ src,
                                         int row0, int tid) {
    const float4* s =
        reinterpret_cast<const float4*>(src + (size_t)row0 * 64);
#pragma unroll
    for (int it = 0; it < 4; it++) {
        int i = tid + it * 256;
        *reinterpret_cast<float4*>(sIn + (i >> 4) * 68 + (i & 15) * 4) = s[i];
    }
}

// 4-output matvec + sigmoid; input and weights both in smem.
// q selects output quad (warp-uniform weight LDS -> broadcast, 1 wavefront).
__device__ __forceinline__ void mv4s(const float* __restrict__ sIn,
                                     const float* __restrict__ sW16,
                                     const float* __restrict__ b, int rloc,
                                     int q, float h[4]) {
    ull acc[4] = {0, 0, 0, 0};
    const float* xr = sIn + rloc * 68;
#pragma unroll 4
    for (int k = 0; k < 64; k += 4) {
        ulonglong2 xv = *reinterpret_cast<const ulonglong2*>(xr + k);
#pragma unroll
        for (int j = 0; j < 4; j++) {
            ulonglong2 w = *reinterpret_cast<const ulonglong2*>(
                sW16 + (q * 4 + j) * 64 + k);
            ffma2_(acc[j], xv.x, w.x);
            ffma2_(acc[j], xv.y, w.y);
        }
    }
#pragma unroll
    for (int j = 0; j < 4; j++) {
        float2 p = unpk_(acc[j]);
        h[j] = sigmoidf_(p.x + p.y + __ldg(b + q * 4 + j));
    }
}

// Fusion GEMM over one k-half (128 k = 4 ix values), 2 rows x 8 cols/thread,
// all 256 threads active. F[k=(ix*4+iy)*8+t][row] = mx[ix]*m2y[iy]*mz[t].
__device__ __forceinline__ void gemm_half2(
    const float* __restrict__ sW_, const float* __restrict__ sMxd,
    const float* __restrict__ sM2yd, const float* __restrict__ sMzd, int r0,
    int g, int ix0, ull acc[2][4]) {
    ull mz2[2][8];
#pragma unroll
    for (int t = 0; t < 8; t++) {
        ulonglong2 m =
            *reinterpret_cast<const ulonglong2*>(sMzd + t * 128 + 2 * r0);
        mz2[0][t] = m.x;
        mz2[1][t] = m.y;
    }
    ull my2[2][4];
#pragma unroll
    for (int iy = 0; iy < 4; iy++) {
        ulonglong2 y =
            *reinterpret_cast<const ulonglong2*>(sM2yd + iy * 128 + 2 * r0);
        my2[0][iy] = y.x;
        my2[1][iy] = y.y;
    }
#pragma unroll 1
    for (int ixl = 0; ixl < 4; ixl++) {
        ulonglong2 ma = *reinterpret_cast<const ulonglong2*>(
            sMxd + (ix0 + ixl) * 128 + 2 * r0);
#pragma unroll
        for (int iy = 0; iy < 4; iy++) {
            ull P0 = fmul2_(ma.x, my2[0][iy]);
            ull P1 = fmul2_(ma.y, my2[1][iy]);
            const float* wrow = sW_ + (ixl * 4 + iy) * 512 + g * 4;
#pragma unroll
            for (int t = 0; t < 8; t++) {
                ulonglong2 w0 =
                    *reinterpret_cast<const ulonglong2*>(wrow + t * 64);
                ulonglong2 w1 =
                    *reinterpret_cast<const ulonglong2*>(wrow + t * 64 + 32);
                ull f0 = fmul2_(P0, mz2[0][t]);
                ull f1 = fmul2_(P1, mz2[1][t]);
                ffma2_(acc[0][0], f0, w0.x); ffma2_(acc[0][1], f0, w0.y);
                ffma2_(acc[0][2], f0, w1.x); ffma2_(acc[0][3], f0, w1.y);
                ffma2_(acc[1][0], f1, w0.x); ffma2_(acc[1][1], f1, w0.y);
                ffma2_(acc[1][2], f1, w1.x); ffma2_(acc[1][3], f1, w1.y);
            }
        }
    }
}

// Shared layout (floats):
//  sW    @ 0     : 8192   (one 32KB weight half / WngT)
//  sGT   @ 8192  : 8704   ([128 k][68], entry k*68 + r)
//  sMxd  @ 16896 : 1024   ([8][128] dup'd)
//  sM2yd @ 17920 : 512    ([4][128])
//  sMzd  @ 18432 : 1024   ([8][128])
//  sIn   @ 19456 : 4352   ([64][68] staged inputs)
//  sMvW  @ 23808 : 3072   (3 x [16][64] matvec weights)
//  total 26880 floats = 107520 B -> 2 CTAs/SM
#define OFF_GT 8192
#define OFF_MXD 16896
#define OFF_M2YD 17920
#define OFF_MZD 18432
#define OFF_IN 19456
#define OFF_MVW 23808
#define SMEM_FLOATS 26880

__global__ void __launch_bounds__(256, 2) fusion_main(
    const float* __restrict__ a, const float* __restrict__ v,
    const float* __restrict__ l, const float* __restrict__ pa,
    const float* __restrict__ pv, const float* __restrict__ pl,
    const float* __restrict__ mean, const float* __restrict__ Wa,
    const float* __restrict__ ba, const float* __restrict__ Wv,
    const float* __restrict__ bv, const float* __restrict__ Wl,
    const float* __restrict__ bl, const float* __restrict__ Wap,
    const float* __restrict__ bap, const float* __restrict__ Wvp,
    const float* __restrict__ bvp, const float* __restrict__ Wlp,
    const float* __restrict__ blp, const float* __restrict__ bf1,
    const float* __restrict__ bfp1, const float* __restrict__ bng,
    const float* __restrict__ rm1, const float* __restrict__ rm2,
    float* __restrict__ out) {
    extern __shared__ __align__(16) float smem[];
    float* sW_ = smem;
    float* sGT = smem + OFF_GT;
    float* sMxd = smem + OFF_MXD;
    float* sM2yd = smem + OFF_M2YD;
    float* sMzd = smem + OFF_MZD;
    float* sIn = smem + OFF_IN;
    float* sMvW = smem + OFF_MVW;

    const int tid = threadIdx.x;
    const int row0 = blockIdx.x * 64;
    const int wid = tid >> 5, lane = tid & 31;
    const int q = wid & 3;                    // matvec output quad
    const int rloc = (wid >> 2) * 32 + lane;  // matvec row
    const int r0 = (tid >> 3) * 2;            // GEMM rows (2 per thread)
    const int g = tid & 7;                    // GEMM col group
    const int c0 = g * 8;
    float h[4];

    // ---- P0: Wfp1T(A)+mvW -> smem; gated mean -> sGT[64..127]; f2 factors
    copy8(sW_, g_WT[0], tid);
    stage_mvw(sMvW, Wap, Wvp, Wlp, tid);
#pragma unroll
    for (int it = 0; it < 16; it++) {
        int i = tid + it * 256;
        int rr = i >> 6, cc = i & 63;
        sGT[(64 + cc) * 68 + rr] =
            gatef_(__ldg(mean + (row0 + rr) * 64 + cc), __ldg(rm1 + 64 + cc));
    }
    stage_in(sIn, pa, row0, tid);
    __syncthreads();
    mv4s(sIn, sMvW, bap, rloc, q, h);
    st_dup2(sMxd + (2 * q) * 128 + 2 * rloc, fmaxf(h[0], h[1]));
    st_dup2(sMxd + (2 * q + 1) * 128 + 2 * rloc, fmaxf(h[2], h[3]));
    __syncthreads();
    stage_in(sIn, pv, row0, tid);
    __syncthreads();
    mv4s(sIn, sMvW + 1024, bvp, rloc, q, h);
    st_dup2(sM2yd + q * 128 + 2 * rloc,
            fmaxf(fmaxf(h[0], h[1]), fmaxf(h[2], h[3])));
    __syncthreads();
    stage_in(sIn, pl, row0, tid);
    __syncthreads();
    mv4s(sIn, sMvW + 2048, blp, rloc, q, h);
    st_dup2(sMzd + (2 * q) * 128 + 2 * rloc, fmaxf(h[0], h[1]));
    st_dup2(sMzd + (2 * q + 1) * 128 + 2 * rloc, fmaxf(h[2], h[3]));
    __syncthreads();

    // ---- P1: GEMM1 (two k-halves, all 256 threads) -> gate -> sGT[0..63] ----
    {
        ull acc[2][4] = {};
        gemm_half2(sW_, sMxd, sM2yd, sMzd, r0, g, 0, acc);
        __syncthreads();
        copy8(sW_, g_WT[0] + 8192, tid);
        __syncthreads();
        gemm_half2(sW_, sMxd, sM2yd, sMzd, r0, g, 4, acc);
#pragma unroll
        for (int j = 0; j < 4; j++) {
            int ca = c0 + 2 * j, cb = ca + 1;
            float bca = __ldg(bfp1 + ca), bcb = __ldg(bfp1 + cb);
            float rca = __ldg(rm1 + ca), rcb = __ldg(rm1 + cb);
            float2 p0 = unpk_(acc[0][j]);  // row r0: cols (ca, cb)
            float2 p1 = unpk_(acc[1][j]);  // row r0+1
            *reinterpret_cast<float2*>(sGT + ca * 68 + r0) =
                make_float2(gatef_(leakyf_(p0.x + bca), rca),
                            gatef_(leakyf_(p1.x + bca), rca));
            *reinterpret_cast<float2*>(sGT + cb * 68 + r0) =
                make_float2(gatef_(leakyf_(p0.y + bcb), rcb),
                            gatef_(leakyf_(p1.y + bcb), rcb));
        }
        __syncthreads();
    }

    // ---- P2: WngT + mvW(branch1) -> smem; fusion-1 factors ----
    copy8(sW_, g_WngT, tid);
    stage_mvw(sMvW, Wa, Wv, Wl, tid);
    stage_in(sIn, a, row0, tid);
    __syncthreads();
    mv4s(sIn, sMvW, ba, rloc, q, h);
    st_dup2(sMxd + (2 * q) * 128 + 2 * rloc, fmaxf(h[0], h[1]));
    st_dup2(sMxd + (2 * q + 1) * 128 + 2 * rloc, fmaxf(h[2], h[3]));
    __syncthreads();
    stage_in(sIn, v, row0, tid);
    __syncthreads();
    mv4s(sIn, sMvW + 1024, bv, rloc, q, h);
    st_dup2(sM2yd + q * 128 + 2 * rloc,
            fmaxf(fmaxf(h[0], h[1]), fmaxf(h[2], h[3])));
    __syncthreads();
    stage_in(sIn, l, row0, tid);
    __syncthreads();
    mv4s(sIn, sMvW + 2048, bl, rloc, q, h);
    st_dup2(sMzd + (2 * q) * 128 + 2 * rloc, fmaxf(h[0], h[1]));
    st_dup2(sMzd + (2 * q + 1) * 128 + 2 * rloc, fmaxf(h[2], h[3]));
    __syncthreads();

    // ---- P3: GEMM2 (K=128, 2r x 8c, interleaved WngT) -> out[:,0:64] ----
    {
        ull acc2[2][4] = {};
#pragma unroll 4
        for (int k = 0; k < 128; k++) {
            float2 fv = *reinterpret_cast<const float2*>(sGT + k * 68 + r0);
            ull f0 = dup2_(fv.x), f1 = dup2_(fv.y);
            const float* wr = sW_ + k * 64 + g * 4;
            ulonglong2 w0 = *reinterpret_cast<const ulonglong2*>(wr);
            ulonglong2 w1 = *reinterpret_cast<const ulonglong2*>(wr + 32);
            ffma2_(acc2[0][0], f0, w0.x); ffma2_(acc2[0][1], f0, w0.y);
            ffma2_(acc2[0][2], f0, w1.x); ffma2_(acc2[0][3], f0, w1.y);
            ffma2_(acc2[1][0], f1, w0.x); ffma2_(acc2[1][1], f1, w0.y);
            ffma2_(acc2[1][2], f1, w1.x); ffma2_(acc2[1][3], f1, w1.y);
        }
        float4 bbA = __ldg(reinterpret_cast<const float4*>(bng + c0));
        float4 bbB = __ldg(reinterpret_cast<const float4*>(bng + c0 + 4));
        float4 rmA = __ldg(reinterpret_cast<const float4*>(rm2 + c0));
        float4 rmB = __ldg(reinterpret_cast<const float4*>(rm2 + c0 + 4));
#pragma unroll
        for (int i = 0; i < 2; i++) {
            float2 p0 = unpk_(acc2[i][0]), p1 = unpk_(acc2[i][1]);
            float2 p2 = unpk_(acc2[i][2]), p3 = unpk_(acc2[i][3]);
            float* orow = out + (row0 + r0 + i) * 128 + c0;
            *reinterpret_cast<float4*>(orow) =
                make_float4(gatef_(p0.x + bbA.x, rmA.x),
                            gatef_(p0.y + bbA.y, rmA.y),
                            gatef_(p1.x + bbA.z, rmA.z),
                            gatef_(p1.y + bbA.w, rmA.w));
            *reinterpret_cast<float4*>(orow + 4) =
                make_float4(gatef_(p2.x + bbB.x, rmB.x),
                            gatef_(p2.y + bbB.y, rmB.y),
                            gatef_(p3.x + bbB.z, rmB.z),
                            gatef_(p3.y + bbB.w, rmB.w));
        }
    }
    __syncthreads();

    // ---- P4: GEMM3 (two k-halves, all 256 threads) -> out[:,64:128] ----
    copy8(sW_, g_WT[1], tid);
    __syncthreads();
    {
        ull acc[2][4] = {};
        gemm_half2(sW_, sMxd, sM2yd, sMzd, r0, g, 0, acc);
        __syncthreads();
        copy8(sW_, g_WT[1] + 8192, tid);
        __syncthreads();
        gemm_half2(sW_, sMxd, sM2yd, sMzd, r0, g, 4, acc);
        float4 bbA = __ldg(reinterpret_cast<const float4*>(bf1 + c0));
        float4 bbB = __ldg(reinterpret_cast<const float4*>(bf1 + c0 + 4));
        float4 rmA = __ldg(reinterpret_cast<const float4*>(rm2 + 64 + c0));
        float4 rmB = __ldg(reinterpret_cast<const float4*>(rm2 + 64 + c0 + 4));
#pragma unroll
        for (int i = 0; i < 2; i++) {
            float2 p0 = unpk_(acc[i][0]), p1 = unpk_(acc[i][1]);
            float2 p2 = unpk_(acc[i][2]), p3 = unpk_(acc[i][3]);
            float* orow = out + (row0 + r0 + i) * 128 + 64 + c0;
            *reinterpret_cast<float4*>(orow) =
                make_float4(gatef_(leakyf_(p0.x + bbA.x), rmA.x),
                            gatef_(leakyf_(p0.y + bbA.y), rmA.y),
                            gatef_(leakyf_(p1.x + bbA.z), rmA.z),
                            gatef_(leakyf_(p1.y + bbA.w), rmA.w));
            *reinterpret_cast<float4*>(orow + 4) =
                make_float4(gatef_(leakyf_(p2.x + bbB.x), rmB.x),
                            gatef_(leakyf_(p2.y + bbB.y), rmB.y),
                            gatef_(leakyf_(p3.x + bbB.z), rmB.z),
                            gatef_(leakyf_(p3.y + bbB.w), rmB.w));
        }
    }
}

extern "C" void kernel_launch(void* const* d_in, const int* in_sizes, int n_in,
                              void* d_out, int out_size) {
    const float* a    = (const float*)d_in[0];
    const float* v    = (const float*)d_in[1];
    const float* l    = (const float*)d_in[2];
    const float* pa   = (const float*)d_in[3];
    const float* pv   = (const float*)d_in[4];
    const float* pl   = (const float*)d_in[5];
    const float* mean = (const float*)d_in[6];
    const float* Wa   = (const float*)d_in[7];
    const float* ba   = (const float*)d_in[8];
    const float* Wv   = (const float*)d_in[9];
    const float* bv   = (const float*)d_in[10];
    const float* Wl   = (const float*)d_in[11];
    const float* bl   = (const float*)d_in[12];
    const float* Wap  = (const float*)d_in[13];
    const float* bap  = (const float*)d_in[14];
    const float* Wvp  = (const float*)d_in[15];
    const float* bvp  = (const float*)d_in[16];
    const float* Wlp  = (const float*)d_in[17];
    const float* blp  = (const float*)d_in[18];
    const float* Wf1  = (const float*)d_in[19];
    const float* bf1  = (const float*)d_in[20];
    const float* Wfp1 = (const float*)d_in[21];
    const float* bfp1 = (const float*)d_in[22];
    const float* Wng  = (const float*)d_in[23];
    const float* bng  = (const float*)d_in[24];
    const float* rm1  = (const float*)d_in[25];
    const float* rm2  = (const float*)d_in[26];

    int nrows = in_sizes[0] / 64;
    static int smem_set = 0;
    if (!smem_set) {
        cudaFuncSetAttribute(fusion_main,
                             cudaFuncAttributeMaxDynamicSharedMemorySize,
                             SMEM_FLOATS * 4);
        smem_set = 1;
    }

    setup_kernel<<<64, 256>>>(Wfp1, Wf1, Wng);
    fusion_main<<<nrows / 64, 256, SMEM_FLOATS * 4>>>(
        a, v, l, pa, pv, pl, mean, Wa, ba, Wv, bv, Wl, bl, Wap, bap, Wvp, bvp,
        Wlp, blp, bf1, bfp1, bng, rm1, rm2, (float*)d_out);
}